// round 1
// baseline (speedup 1.0000x reference)
#include <cuda_runtime.h>

#define TT 8
#define G  16
#define GG 256
#define DD 64
#define THRS 0.5f

// accumulators: 0 wl, 1 pool, 2 obj, 3 pres, 4 flowsq, 5 sumzp, 6 sumflow
__device__ double g_acc[8];

__device__ __forceinline__ float wsum(float v) {
#pragma unroll
    for (int s = 16; s > 0; s >>= 1) v += __shfl_xor_sync(0xffffffffu, v, s);
    return v;
}

__global__ void zero_kernel() {
    if (threadIdx.x < 8) g_acc[threadIdx.x] = 0.0;
}

// One block per (t, t+1, b) pair. Computes z_what_loss, pool term, objects term.
__global__ __launch_bounds__(512, 1) void main_kernel(const float* __restrict__ zw,
                                                      const float* __restrict__ zp,
                                                      int B) {
    extern __shared__ float sm[];
    float* s0 = sm;              // frame t   [GG][DD]
    float* s1 = sm + GG * DD;    // frame t+1 [GG][DD]
    float* p0 = s1 + GG * DD;    // zp frame t
    float* p1 = p0 + GG;         // zp frame t+1
    float* n1 = p1 + GG;         // ||s1[c]||^2
    __shared__ double rd[3];

    int pair = blockIdx.x;
    int b = pair % B, t = pair / B;
    size_t base0 = ((size_t)(t * B + b)) * (GG * DD);
    size_t base1 = ((size_t)((t + 1) * B + b)) * (GG * DD);
    int tid = threadIdx.x;

    const float4* g0 = (const float4*)(zw + base0);
    const float4* g1 = (const float4*)(zw + base1);
    for (int k = tid; k < GG * DD / 4; k += 512) {
        ((float4*)s0)[k] = g0[k];
        ((float4*)s1)[k] = g1[k];
    }
    if (tid < GG)            p0[tid]      = zp[(size_t)(t * B + b) * GG + tid];
    else if (tid < 2 * GG)   p1[tid - GG] = zp[(size_t)((t + 1) * B + b) * GG + (tid - GG)];
    if (tid < 3) rd[tid] = 0.0;
    __syncthreads();

    int lane = tid & 31, w = tid >> 5;

    // norms of frame t+1 cells
    for (int c = w; c < GG; c += 16) {
        float2 v = ((const float2*)(s1 + c * DD))[lane];
        float s = wsum(v.x * v.x + v.y * v.y);
        if (lane == 0) n1[c] = s;
    }
    __syncthreads();

    float wl = 0.f, obj = 0.f, pool = 0.f;

    for (int c = w * 16; c < w * 16 + 16; ++c) {
        int i = c >> 4, j = c & 15;
        float2 pr = ((const float2*)(s0 + c * DD))[lane];

        float red[13];
        float nnv[9];
        bool  nbp[9];
        float2 m;  m.x = -INFINITY; m.y = -INFINITY;
        float2 ctr1 = make_float2(0.f, 0.f);

        int k = 0;
#pragma unroll
        for (int di = -1; di <= 1; ++di) {
#pragma unroll
            for (int dj = -1; dj <= 1; ++dj, ++k) {
                // objects term: wrapped neighbor in frame t+1 (jnp.roll semantics)
                int iw = (i + di) & 15, jw = (j + dj) & 15;
                int nw = iw * G + jw;
                float2 nb = ((const float2*)(s1 + nw * DD))[lane];
                if (di == 0 && dj == 0) ctr1 = nb;
                red[k] = pr.x * nb.x + pr.y * nb.y;
                nnv[k] = n1[nw];
                nbp[k] = p1[nw] > THRS;
                // pool term: valid-only (zero-padded) maxpool over frame t of |zw|*zp
                int ii = i + di, jj = j + dj;
                if (ii >= 0 && ii < G && jj >= 0 && jj < G) {
                    int nc = ii * G + jj;
                    float2 a = ((const float2*)(s0 + nc * DD))[lane];
                    float pz = p0[nc];
                    m.x = fmaxf(m.x, fabsf(a.x) * pz);
                    m.y = fmaxf(m.y, fabsf(a.y) * pz);
                }
            }
        }

        float2 wc;
        wc.x = fabsf(ctr1.x) * p1[c];
        wc.y = fabsf(ctr1.y) * p1[c];
        red[9]  = pr.x * pr.x + pr.y * pr.y;   // prior norm^2
        red[10] = m.x * wc.x + m.y * wc.y;     // pooled dot
        red[11] = m.x * m.x + m.y * m.y;       // na^2
        red[12] = wc.x * wc.x + wc.y * wc.y;   // nb^2

        // batched butterfly reduction of all 13 scalars (ILP across chains)
#pragma unroll
        for (int s = 16; s > 0; s >>= 1) {
#pragma unroll
            for (int q = 0; q < 13; ++q)
                red[q] += __shfl_xor_sync(0xffffffffu, red[q], s);
        }

        float prior_n = fmaxf(sqrtf(red[9]), 1e-8f);
        float sum_sim = 0.f, max_sim = -INFINITY;
        bool has = false;
#pragma unroll
        for (int q = 0; q < 9; ++q) {
            float s = red[q] / (prior_n * fmaxf(sqrtf(nnv[q]), 1e-8f));
            if (nbp[q]) {
                sum_sim += s;
                max_sim = fmaxf(max_sim, s);
                has = true;
            }
        }

        if (lane == 0) {
            if (p0[c] > THRS && has) obj += (-5.0f * max_sim + sum_sim);
            float cosn = red[10] / (fmaxf(sqrtf(red[11]), 1e-6f) * fmaxf(sqrtf(red[12]), 1e-6f));
            pool -= cosn * 0.5f * (p0[c] + p1[c]);
        }

        float dx = ctr1.x - pr.x, dy = ctr1.y - pr.y;
        wl += dx * dx + dy * dy;
    }

    float wlw = wsum(wl);
    if (lane == 0) {
        atomicAdd(&rd[0], (double)wlw);
        atomicAdd(&rd[1], (double)pool);
        atomicAdd(&rd[2], (double)obj);
    }
    __syncthreads();
    if (tid == 0) {
        atomicAdd(&g_acc[0], rd[0]);
        atomicAdd(&g_acc[1], rd[1]);
        atomicAdd(&g_acc[2], rd[2]);
    }
}

// One block per (t,b) image: z_pres triples, flow mask term, global sums.
__global__ __launch_bounds__(256) void pf_kernel(const float* __restrict__ zp,
                                                 const float* __restrict__ fl,
                                                 int B) {
    __shared__ float sp[GG];
    __shared__ double rd[4];
    int n = blockIdx.x;
    int t = n / B, b = n % B;
    int c = threadIdx.x;

    float zpc = zp[(size_t)n * GG + c];
    sp[c] = zpc;
    if (c < 4) rd[c] = 0.0;
    __syncthreads();

    int i = c >> 4, j = c & 15;
    float mx = -INFINITY;
#pragma unroll
    for (int di = -1; di <= 1; ++di) {
        int ii = i + di;
        if (ii < 0 || ii >= G) continue;
#pragma unroll
        for (int dj = -1; dj <= 1; ++dj) {
            int jj = j + dj;
            if (jj < 0 || jj >= G) continue;
            mx = fmaxf(mx, sp[ii * G + jj]);
        }
    }

    float f = fl[(size_t)n * GG + c];
    float fsq = (f > 0.5f) ? (mx - f) * (mx - f) : 0.f;

    float pres = 0.f;
    if (t >= 1 && t <= TT - 2) {
        float za = zp[(size_t)((t - 1) * B + b) * GG + c];
        float zb = zp[(size_t)((t + 1) * B + b) * GG + c];
        float dba = zb - za;
        float sim = 1.f - dba * dba;
        float d1 = zb - zpc, d2 = za - zpc;
        pres = sim * (d1 * d1 + d2 * d2);
    }

    float v0 = wsum(fsq), v1 = wsum(zpc), v2 = wsum(f), v3 = wsum(pres);
    if ((c & 31) == 0) {
        atomicAdd(&rd[0], (double)v0);
        atomicAdd(&rd[1], (double)v1);
        atomicAdd(&rd[2], (double)v2);
        atomicAdd(&rd[3], (double)v3);
    }
    __syncthreads();
    if (c == 0) {
        atomicAdd(&g_acc[4], rd[0]);
        atomicAdd(&g_acc[5], rd[1]);
        atomicAdd(&g_acc[6], rd[2]);
        atomicAdd(&g_acc[3], rd[3]);
    }
}

__global__ void fin_kernel(const void* __restrict__ gs, float* __restrict__ out) {
    int gi = *(const int*)gs;
    double gstep;
    if (gi < 0 || gi > 1000000000) gstep = (double)__int_as_float(gi);  // defensive: fp32-encoded step
    else gstep = (double)gi;

    double scale_obj = gstep / 200000.0;  if (scale_obj > 1.0) scale_obj = 1.0;
    double scale_flow = 1.0 - gstep / 100000.0;  if (scale_flow < 0.0) scale_flow = 0.0;

    double hinge = g_acc[5] - g_acc[6];
    if (hinge < 0.0) hinge = 0.0;
    double flow_loss = g_acc[4] + 100.0 * hinge;

    double loss = g_acc[0]                      // z_what_loss * ADJ_W(1)
                + g_acc[3]                      // z_pres_loss * PRES_W(1)
                + g_acc[1]                      // pool * POOL_W(1)
                + g_acc[2] * scale_obj * 10.0   // objects * scale * OBJ_W
                + flow_loss * scale_flow;       // FLOW_W(1)
    out[0] = (float)loss;
}

extern "C" void kernel_launch(void* const* d_in, const int* in_sizes, int n_in,
                              void* d_out, int out_size) {
    const float* zw = (const float*)d_in[0];
    const float* zp = (const float*)d_in[1];
    const float* fl = (const float*)d_in[2];
    const void*  gs = d_in[3];
    int B = in_sizes[0] / (TT * GG * DD);

    const int SMEM_BYTES = (2 * GG * DD + 3 * GG) * (int)sizeof(float);
    cudaFuncSetAttribute(main_kernel, cudaFuncAttributeMaxDynamicSharedMemorySize, SMEM_BYTES);

    zero_kernel<<<1, 32>>>();
    main_kernel<<<(TT - 1) * B, 512, SMEM_BYTES>>>(zw, zp, B);
    pf_kernel<<<TT * B, 256>>>(zp, fl, B);
    fin_kernel<<<1, 1>>>(gs, (float*)d_out);
}

// round 2
// speedup vs baseline: 3.1713x; 3.1713x over previous
#include <cuda_runtime.h>

#define TT 8
#define G  16
#define GG 256
#define DD 64
#define S4 17          // float4 row stride (68 floats) -> conflict-free LDS
#define THRS 0.5f

// 0 wl, 1 pool, 2 obj, 3 pres, 4 flowsq, 5 sumzp, 6 sumflow  (zero-init at load,
// reset by the finalize step each run so graph replays stay deterministic)
__device__ double g_acc[8];
__device__ unsigned g_ctr;

__device__ __forceinline__ float wsum(float v) {
#pragma unroll
    for (int s = 16; s > 0; s >>= 1) v += __shfl_xor_sync(0xffffffffu, v, s);
    return v;
}

// One block per (t,t+1,b) pair; thread = grid cell. No per-D shuffles.
__global__ __launch_bounds__(256, 1) void main_kernel(const float* __restrict__ zw,
                                                      const float* __restrict__ zp,
                                                      int B) {
    extern __shared__ float4 sm4[];
    float4* s0  = sm4;               // frame t   [GG][S4]
    float4* s1  = s0 + GG * S4;      // frame t+1
    float4* rmx = s1 + GG * S4;      // row-max of |s0|*p0
    float*  p0s = (float*)(rmx + GG * S4);
    float*  p1s = p0s + GG;
    float*  n1s = p1s + GG;
    __shared__ double rd[3];

    int pair = blockIdx.x;
    int b = pair % B, t = pair / B;
    int c = threadIdx.x;
    int i = c >> 4, j = c & 15;

    size_t f0 = (size_t)(t * B + b);
    size_t f1 = (size_t)((t + 1) * B + b);
    const float4* g0 = (const float4*)(zw + f0 * (GG * DD));
    const float4* g1 = (const float4*)(zw + f1 * (GG * DD));

    p0s[c] = zp[f0 * GG + c];
    p1s[c] = zp[f1 * GG + c];
    if (c < 3) rd[c] = 0.0;

#pragma unroll
    for (int k = 0; k < 16; ++k) {
        int idx = k * 256 + c;           // coalesced float4 index in frame
        int row = idx >> 4, d4 = idx & 15;
        s0[row * S4 + d4] = g0[idx];
        s1[row * S4 + d4] = g1[idx];
    }
    __syncthreads();

    // ---- separable maxpool pass: rmx[c] = max over cols j-1..j+1 of |s0|*p0 ----
    // (all values >= 0, so a zero weight safely ignores out-of-range columns)
    {
        int cm = (j > 0) ? c - 1 : c;
        int cp = (j < 15) ? c + 1 : c;
        float pzm = (j > 0) ? p0s[cm] : 0.f;
        float pz0 = p0s[c];
        float pzp = (j < 15) ? p0s[cp] : 0.f;
#pragma unroll
        for (int d = 0; d < 16; ++d) {
            float4 am = s0[cm * S4 + d];
            float4 a0 = s0[c  * S4 + d];
            float4 ap = s0[cp * S4 + d];
            float4 m;
            m.x = fmaxf(fmaxf(fabsf(am.x) * pzm, fabsf(a0.x) * pz0), fabsf(ap.x) * pzp);
            m.y = fmaxf(fmaxf(fabsf(am.y) * pzm, fabsf(a0.y) * pz0), fabsf(ap.y) * pzp);
            m.z = fmaxf(fmaxf(fabsf(am.z) * pzm, fabsf(a0.z) * pz0), fabsf(ap.z) * pzp);
            m.w = fmaxf(fmaxf(fabsf(am.w) * pzm, fabsf(a0.w) * pz0), fabsf(ap.w) * pzp);
            rmx[c * S4 + d] = m;
        }
    }
    __syncthreads();

    // ---- precompute 9 wrapped neighbor cells (frame t+1) + pres mask ----
    int nidx[9];
    unsigned pmask = 0;
    {
        int k = 0;
#pragma unroll
        for (int di = -1; di <= 1; ++di)
#pragma unroll
            for (int dj = -1; dj <= 1; ++dj, ++k) {
                int nc = ((i + di) & 15) * 16 + ((j + dj) & 15);
                nidx[k] = nc;
                if (p1s[nc] > THRS) pmask |= (1u << k);
            }
    }
    int ru  = (i > 0)  ? c - 16 : c;   // duplicate center when clamped: max unchanged
    int rdn = (i < 15) ? c + 16 : c;
    float p1c = p1s[c];

    float dot[9] = {0.f, 0.f, 0.f, 0.f, 0.f, 0.f, 0.f, 0.f, 0.f};
    float nrm = 0.f, cn = 0.f, wl = 0.f, pd = 0.f, na = 0.f, nb2 = 0.f;

#pragma unroll
    for (int d = 0; d < 16; ++d) {
        float4 p = s0[c * S4 + d];
        float4 ctr;
#pragma unroll
        for (int k = 0; k < 9; ++k) {
            float4 v = s1[nidx[k] * S4 + d];
            dot[k] += p.x * v.x;
            dot[k] += p.y * v.y;
            dot[k] += p.z * v.z;
            dot[k] += p.w * v.w;
            if (k == 4) ctr = v;
        }
        nrm += p.x * p.x + p.y * p.y + p.z * p.z + p.w * p.w;
        cn  += ctr.x * ctr.x + ctr.y * ctr.y + ctr.z * ctr.z + ctr.w * ctr.w;
        float dx = ctr.x - p.x, dy = ctr.y - p.y, dz = ctr.z - p.z, dw = ctr.w - p.w;
        wl += dx * dx + dy * dy + dz * dz + dw * dw;
        float4 wc;
        wc.x = fabsf(ctr.x) * p1c;
        wc.y = fabsf(ctr.y) * p1c;
        wc.z = fabsf(ctr.z) * p1c;
        wc.w = fabsf(ctr.w) * p1c;
        float4 mu = rmx[ru * S4 + d], mc = rmx[c * S4 + d], md = rmx[rdn * S4 + d];
        float4 m;
        m.x = fmaxf(fmaxf(mu.x, mc.x), md.x);
        m.y = fmaxf(fmaxf(mu.y, mc.y), md.y);
        m.z = fmaxf(fmaxf(mu.z, mc.z), md.z);
        m.w = fmaxf(fmaxf(mu.w, mc.w), md.w);
        pd  += m.x * wc.x + m.y * wc.y + m.z * wc.z + m.w * wc.w;
        na  += m.x * m.x + m.y * m.y + m.z * m.z + m.w * m.w;
        nb2 += wc.x * wc.x + wc.y * wc.y + wc.z * wc.z + wc.w * wc.w;
    }

    n1s[c] = cn;                 // ||s1[c]||^2, consumed by the 8 neighbors
    __syncthreads();

    float prior_n = fmaxf(sqrtf(nrm), 1e-8f);
    float ssum = 0.f, smax = -INFINITY;
#pragma unroll
    for (int k = 0; k < 9; ++k) {
        float nn = fmaxf(sqrtf(n1s[nidx[k]]), 1e-8f);
        float s = __fdividef(dot[k], prior_n * nn);
        if (pmask & (1u << k)) {
            ssum += s;
            smax = fmaxf(smax, s);
        }
    }
    float obj = (p0s[c] > THRS && pmask) ? (-5.0f * smax + ssum) : 0.f;
    float cosp = __fdividef(pd, fmaxf(sqrtf(na), 1e-6f) * fmaxf(sqrtf(nb2), 1e-6f));
    float pool = -cosp * 0.5f * (p0s[c] + p1c);

    wl = wsum(wl); pool = wsum(pool); obj = wsum(obj);
    if ((c & 31) == 0) {
        atomicAdd(&rd[0], (double)wl);
        atomicAdd(&rd[1], (double)pool);
        atomicAdd(&rd[2], (double)obj);
    }
    __syncthreads();
    if (c == 0) {
        atomicAdd(&g_acc[0], rd[0]);
        atomicAdd(&g_acc[1], rd[1]);
        atomicAdd(&g_acc[2], rd[2]);
    }
}

// One block per (t,b) image: pres triples, flow term, global sums; the last
// block to finish also finalizes the loss and resets the accumulators.
__global__ __launch_bounds__(256) void pf_kernel(const float* __restrict__ zp,
                                                 const float* __restrict__ fl,
                                                 const void* __restrict__ gs,
                                                 float* __restrict__ out,
                                                 int B) {
    __shared__ float sp[GG];
    __shared__ double rd[4];
    __shared__ unsigned isLast;
    int n = blockIdx.x;
    int t = n / B, b = n % B;
    int c = threadIdx.x;

    float zpc = zp[(size_t)n * GG + c];
    sp[c] = zpc;
    if (c < 4) rd[c] = 0.0;
    __syncthreads();

    int i = c >> 4, j = c & 15;
    float mx = -INFINITY;
#pragma unroll
    for (int di = -1; di <= 1; ++di) {
        int ii = i + di;
        if (ii < 0 || ii >= G) continue;
#pragma unroll
        for (int dj = -1; dj <= 1; ++dj) {
            int jj = j + dj;
            if (jj < 0 || jj >= G) continue;
            mx = fmaxf(mx, sp[ii * G + jj]);
        }
    }

    float f = fl[(size_t)n * GG + c];
    float fsq = (f > 0.5f) ? (mx - f) * (mx - f) : 0.f;

    float pres = 0.f;
    if (t >= 1 && t <= TT - 2) {
        float za = zp[(size_t)((t - 1) * B + b) * GG + c];
        float zb = zp[(size_t)((t + 1) * B + b) * GG + c];
        float dba = zb - za;
        float sim = 1.f - dba * dba;
        float d1 = zb - zpc, d2 = za - zpc;
        pres = sim * (d1 * d1 + d2 * d2);
    }

    float v0 = wsum(fsq), v1 = wsum(zpc), v2 = wsum(f), v3 = wsum(pres);
    if ((c & 31) == 0) {
        atomicAdd(&rd[0], (double)v0);
        atomicAdd(&rd[1], (double)v1);
        atomicAdd(&rd[2], (double)v2);
        atomicAdd(&rd[3], (double)v3);
    }
    __syncthreads();
    if (c == 0) {
        atomicAdd(&g_acc[4], rd[0]);
        atomicAdd(&g_acc[5], rd[1]);
        atomicAdd(&g_acc[6], rd[2]);
        atomicAdd(&g_acc[3], rd[3]);
        __threadfence();
        unsigned old = atomicAdd(&g_ctr, 1u);
        isLast = (old == gridDim.x - 1) ? 1u : 0u;
    }
    __syncthreads();

    if (isLast && c == 0) {
        __threadfence();
        int gi = *(const int*)gs;
        double gstep;
        if (gi < 0 || gi > 1000000000) gstep = (double)__int_as_float(gi);
        else gstep = (double)gi;

        double scale_obj = gstep / 200000.0;  if (scale_obj > 1.0) scale_obj = 1.0;
        double scale_flow = 1.0 - gstep / 100000.0;  if (scale_flow < 0.0) scale_flow = 0.0;

        double hinge = g_acc[5] - g_acc[6];
        if (hinge < 0.0) hinge = 0.0;
        double flow_loss = g_acc[4] + 100.0 * hinge;

        double loss = g_acc[0]                       // z_what_loss (ADJ_W=1)
                    + g_acc[3]                       // z_pres_loss (PRES_W=1)
                    + g_acc[1]                       // pool (POOL_W=1)
                    + g_acc[2] * scale_obj * 10.0    // objects * OBJ_W
                    + flow_loss * scale_flow;        // FLOW_W=1
        out[0] = (float)loss;

        // reset for the next graph replay
#pragma unroll
        for (int q = 0; q < 8; ++q) g_acc[q] = 0.0;
        g_ctr = 0u;
    }
}

extern "C" void kernel_launch(void* const* d_in, const int* in_sizes, int n_in,
                              void* d_out, int out_size) {
    const float* zw = (const float*)d_in[0];
    const float* zp = (const float*)d_in[1];
    const float* fl = (const float*)d_in[2];
    const void*  gs = d_in[3];
    int B = in_sizes[0] / (TT * GG * DD);

    const int SMEM_BYTES = (3 * GG * S4) * (int)sizeof(float4) + 3 * GG * (int)sizeof(float);
    static int configured = 0;
    if (!configured) {
        cudaFuncSetAttribute(main_kernel, cudaFuncAttributeMaxDynamicSharedMemorySize, SMEM_BYTES);
        configured = 1;
    }

    main_kernel<<<(TT - 1) * B, 256, SMEM_BYTES>>>(zw, zp, B);
    pf_kernel<<<TT * B, 256>>>(zp, fl, gs, (float*)d_out, B);
}